// round 16
// baseline (speedup 1.0000x reference)
#include <cuda_runtime.h>
#include <cuda_bf16.h>

#define N_NODES 50000
#define N_EDGES 800000
#define LATDIM  128

typedef unsigned long long ull;

// ---- scratch (static device globals: the sanctioned no-alloc workaround) ----
__device__ float g_Q[N_NODES * LATDIM];
__device__ float g_K[N_NODES * LATDIM];
__device__ float g_V[N_NODES * LATDIM];
__device__ int   g_cnt[N_NODES];       // zero-init; re-zeroed by scan each run
__device__ int   g_bsum[64];           // lookback slots: 0 = unpublished, else total+1
__device__ int   g_rowptr[N_NODES + 1];
__device__ int   g_fill[N_NODES];
__device__ int   g_adj[N_EDGES];

// ---- packed f32x2 helpers (base sm_103 PTX — no 'a' features) ----
__device__ __forceinline__ ull pack2(float lo, float hi) {
    ull r;
    asm("mov.b64 %0, {%1, %2};" : "=l"(r)
        : "r"(__float_as_uint(lo)), "r"(__float_as_uint(hi)));
    return r;
}
__device__ __forceinline__ void fma2(ull& d, ull a, ull b) {
    asm("fma.rn.f32x2 %0, %1, %2, %3;" : "=l"(d) : "l"(a), "l"(b), "l"(d));
}
__device__ __forceinline__ void unpack2(ull v, float& lo, float& hi) {
    unsigned ulo, uhi;
    asm("mov.b64 {%0, %1}, %2;" : "=r"(ulo), "=r"(uhi) : "l"(v));
    lo = __uint_as_float(ulo);
    hi = __uint_as_float(uhi);
}

// ============================================================
// Kernel 1: fused Q/K/V projection + edge histogram.
// grid = (ceil(N/64), 4): y<3 GEMM slices, y==3 histogram.
//
// OCCUPANCY-3 variant of the locked-in scalar FFMA2 GEMM: tile is
// 64 rows x 128 cols per block (4 rows x 8 cols per thread), so acc
// shrinks 64 -> 32 regs and regs/thread ~80 -> 3 blocks/SM = 24
// warps (was 16 at the 128-row tile). Issue mix is unchanged (~59%
// fma share is tile-invariant for the A-packed-in-regs scheme); the
// extra warps close the latency-exposure gap that held fma-pipe at
// 60% of peak (floor = 104us x 0.602 ~ 63us).
// LDS patterns preserved from R10: A broadcast, B contiguous 256B.
// ============================================================
__global__ __launch_bounds__(256, 3)
void gemm3_hist_kernel(const float* __restrict__ E,
                       const float* __restrict__ qW,
                       const float* __restrict__ kW,
                       const float* __restrict__ vW,
                       const int* __restrict__ rows,
                       int N, int nE)
{
    // --- histogram slice: scheduled after GEMM blocks, fills the tail wave ---
    if (blockIdx.y == 3) {
        int stride = gridDim.x * blockDim.x;
        for (int e = blockIdx.x * blockDim.x + threadIdx.x; e < nE; e += stride)
            atomicAdd(&g_cnt[rows[e]], 1);
        return;
    }

    __shared__ float As[32][68];    // A tile transposed: As[k][row]  (64 rows)
    __shared__ float Bs[32][128];   // W tile: Bs[k][col]

    const float* W   = (blockIdx.y == 0) ? qW : (blockIdx.y == 1 ? kW : vW);
    float*       Out = (blockIdx.y == 0) ? g_Q : (blockIdx.y == 1 ? g_K : g_V);

    const int row0 = blockIdx.x * 64;
    const int tid  = threadIdx.x;
    const int tr   = (tid >> 4) << 2;   // thread row base (0..60), 4 rows
    const int tc   = (tid & 15) << 2;   // col blocks [tc,tc+4) and [tc+64,tc+68)
    const int kq   = (tid & 7) * 4;     // A-load k offset
    const int rb   = tid >> 3;          // A-load row base (0..31)

    ull acc[4][4];
#pragma unroll
    for (int i = 0; i < 4; i++)
#pragma unroll
        for (int j = 0; j < 4; j++) acc[i][j] = 0ULL;

    // prefetch A chunk 0 into registers (2 row-blocks of 32)
    float4 aq[2];
#pragma unroll
    for (int rr = 0; rr < 2; rr++) {
        int grow = row0 + rb + rr * 32;
        aq[rr] = (grow < N)
            ? __ldg((const float4*)(E + (size_t)grow * LATDIM + kq))
            : make_float4(0.f, 0.f, 0.f, 0.f);
    }

    for (int c = 0; c < 4; c++) {
        const int kc = c * 32;
        __syncthreads();                // previous chunk's compute fully done

        // B chunk load + store (W is L2-resident after wave 1)
#pragma unroll
        for (int v = tid; v < 32 * 32; v += 256) {
            int k = v >> 5, c4 = v & 31;
            *(float4*)&Bs[k][c4 * 4] =
                __ldg((const float4*)(W + (size_t)(kc + k) * LATDIM) + c4);
        }
        // A chunk store from prefetched registers (transposed)
#pragma unroll
        for (int rr = 0; rr < 2; rr++) {
            int r = rb + rr * 32;
            As[kq + 0][r] = aq[rr].x;
            As[kq + 1][r] = aq[rr].y;
            As[kq + 2][r] = aq[rr].z;
            As[kq + 3][r] = aq[rr].w;
        }
        __syncthreads();

        // issue next chunk's A LDGs now — latency hides under compute below
        if (c < 3) {
#pragma unroll
            for (int rr = 0; rr < 2; rr++) {
                int grow = row0 + rb + rr * 32;
                aq[rr] = (grow < N)
                    ? __ldg((const float4*)(E + (size_t)grow * LATDIM + kc + 32 + kq))
                    : make_float4(0.f, 0.f, 0.f, 0.f);
            }
        }

#pragma unroll 8
        for (int k = 0; k < 32; k++) {
            float4 a0 = *(const float4*)&As[k][tr];        // broadcast (2/warp)
            ulonglong2 bq0 = *(const ulonglong2*)&Bs[k][tc];       // contiguous
            ulonglong2 bq1 = *(const ulonglong2*)&Bs[k][tc + 64];  // contiguous
            ull bb[4] = {bq0.x, bq0.y, bq1.x, bq1.y};
            ull aa[4];
            aa[0] = pack2(a0.x, a0.x);
            aa[1] = pack2(a0.y, a0.y);
            aa[2] = pack2(a0.z, a0.z);
            aa[3] = pack2(a0.w, a0.w);
#pragma unroll
            for (int i = 0; i < 4; i++) {
                fma2(acc[i][0], aa[i], bb[0]);
                fma2(acc[i][1], aa[i], bb[1]);
                fma2(acc[i][2], aa[i], bb[2]);
                fma2(acc[i][3], aa[i], bb[3]);
            }
        }
    }

#pragma unroll
    for (int i = 0; i < 4; i++) {
        int grow = row0 + tr + i;
        if (grow < N) {
            float o[8];
#pragma unroll
            for (int j = 0; j < 4; j++) unpack2(acc[i][j], o[2 * j], o[2 * j + 1]);
            *(float4*)(Out + (size_t)grow * LATDIM + tc)      = make_float4(o[0], o[1], o[2], o[3]);
            *(float4*)(Out + (size_t)grow * LATDIM + tc + 64) = make_float4(o[4], o[5], o[6], o[7]);
        }
    }
}

// ============================================================
// Single-launch exclusive scan with inter-block lookback (49 blocks,
// all co-resident: 49 < 148 SMs, spin-wait deadlock-free).
// (R15's scan+scatter fusion regressed: 49-block scatter lost MLP.)
// ============================================================
__global__ __launch_bounds__(1024)
void scan_fused(int n) {
    __shared__ int warp_sums[32];
    __shared__ int s_offset;
    const int tid  = threadIdx.x;
    const int lane = tid & 31;
    const int wid  = tid >> 5;
    const int bid  = blockIdx.x;
    const int i    = bid * 1024 + tid;

    int v = (i < n) ? g_cnt[i] : 0;

    int s = v;
#pragma unroll
    for (int o = 1; o < 32; o <<= 1) {
        int t = __shfl_up_sync(0xffffffffu, s, o);
        if (lane >= o) s += t;
    }
    if (lane == 31) warp_sums[wid] = s;
    __syncthreads();
    if (wid == 0) {
        int w = warp_sums[lane];
#pragma unroll
        for (int o = 1; o < 32; o <<= 1) {
            int t = __shfl_up_sync(0xffffffffu, w, o);
            if (lane >= o) w += t;
        }
        warp_sums[lane] = w;
    }
    __syncthreads();
    int incl = s + (wid > 0 ? warp_sums[wid - 1] : 0);

    if (tid == 1023) atomicExch(&g_bsum[bid], incl + 1);
    if (tid == 0) s_offset = 0;
    __syncthreads();

    if (tid < bid) {
        int pv;
        do { pv = atomicAdd(&g_bsum[tid], 0); } while (pv == 0);
        atomicAdd(&s_offset, pv - 1);
    }
    __syncthreads();

    int r = s_offset + incl - v;
    if (i < n) {
        g_rowptr[i] = r;
        g_fill[i]   = r;
        g_cnt[i]    = 0;           // re-zero for next call's fused histogram
    } else if (i == n) {
        g_rowptr[n] = r;
    }
}

__global__ void scatter_kernel(const int* __restrict__ rows,
                               const int* __restrict__ cols, int nE) {
    int e = blockIdx.x * blockDim.x + threadIdx.x;
    if (e < 64) g_bsum[e] = 0;     // reset lookback slots for next call
    if (e < nE) {
        int r = rows[e];
        int pos = atomicAdd(&g_fill[r], 1);
        g_adj[pos] = cols[e];
    }
}

// ============================================================
// Kernel 2: fused per-node attention. One warp per node, 2-edge
// unroll (measured optimum: 4-edge raised regs 40->55, occ fell to
// 42%, regressed; 2-edge is the knee of the MLP/occupancy tradeoff).
// ============================================================
__global__ void attn_kernel(float* __restrict__ out, int N) {
    int warp = (blockIdx.x * blockDim.x + threadIdx.x) >> 5;
    int lane = threadIdx.x & 31;
    if (warp >= N) return;

    const float4 q = __ldg((const float4*)(g_Q + (size_t)warp * LATDIM) + lane);
    int beg = g_rowptr[warp];
    int end = g_rowptr[warp + 1];

    float ax = 0.f, ay = 0.f, az = 0.f, aw = 0.f, denom = 0.f;

    int i = beg;
    for (; i + 2 <= end; i += 2) {
        int c0 = __ldg(g_adj + i);
        int c1 = __ldg(g_adj + i + 1);
        const float4 k0 = __ldg((const float4*)(g_K + (size_t)c0 * LATDIM) + lane);
        const float4 v0 = __ldg((const float4*)(g_V + (size_t)c0 * LATDIM) + lane);
        const float4 k1 = __ldg((const float4*)(g_K + (size_t)c1 * LATDIM) + lane);
        const float4 v1 = __ldg((const float4*)(g_V + (size_t)c1 * LATDIM) + lane);

        float p0 = q.x * k0.x + q.y * k0.y + q.z * k0.z + q.w * k0.w;
        float p1 = q.x * k1.x + q.y * k1.y + q.z * k1.z + q.w * k1.w;
        p0 += __shfl_xor_sync(0xffffffffu, p0, 1);
        p1 += __shfl_xor_sync(0xffffffffu, p1, 1);
        p0 += __shfl_xor_sync(0xffffffffu, p0, 2);
        p1 += __shfl_xor_sync(0xffffffffu, p1, 2);
        p0 += __shfl_xor_sync(0xffffffffu, p0, 4);
        p1 += __shfl_xor_sync(0xffffffffu, p1, 4);
        p0 = fminf(fmaxf(p0, -10.f), 10.f);
        p1 = fminf(fmaxf(p1, -10.f), 10.f);
        float e0 = __expf(p0);
        float e1 = __expf(p1);
        denom += e0 + e1;
        ax = fmaf(e0, v0.x, ax); ax = fmaf(e1, v1.x, ax);
        ay = fmaf(e0, v0.y, ay); ay = fmaf(e1, v1.y, ay);
        az = fmaf(e0, v0.z, az); az = fmaf(e1, v1.z, az);
        aw = fmaf(e0, v0.w, aw); aw = fmaf(e1, v1.w, aw);
    }
    if (i < end) {
        int c = __ldg(g_adj + i);
        const float4 k4 = __ldg((const float4*)(g_K + (size_t)c * LATDIM) + lane);
        const float4 v4 = __ldg((const float4*)(g_V + (size_t)c * LATDIM) + lane);
        float p = q.x * k4.x + q.y * k4.y + q.z * k4.z + q.w * k4.w;
        p += __shfl_xor_sync(0xffffffffu, p, 1);
        p += __shfl_xor_sync(0xffffffffu, p, 2);
        p += __shfl_xor_sync(0xffffffffu, p, 4);
        p = fminf(fmaxf(p, -10.f), 10.f);
        float e = __expf(p);
        denom += e;
        ax = fmaf(e, v4.x, ax);
        ay = fmaf(e, v4.y, ay);
        az = fmaf(e, v4.z, az);
        aw = fmaf(e, v4.w, aw);
    }

    float inv = 1.f / (denom + 1e-8f);
    float4 o = make_float4(ax * inv, ay * inv, az * inv, aw * inv);
    *((float4*)out + (size_t)warp * 32 + lane) = o;
}

// ============================================================
extern "C" void kernel_launch(void* const* d_in, const int* in_sizes, int n_in,
                              void* d_out, int out_size) {
    const float* E    = (const float*)d_in[0];
    const float* qW   = (const float*)d_in[1];
    const float* kW   = (const float*)d_in[2];
    const float* vW   = (const float*)d_in[3];
    const int*   rows = (const int*)d_in[4];
    const int*   cols = (const int*)d_in[5];

    int N  = in_sizes[0] / LATDIM;
    int Eg = in_sizes[4];

    int nb = (N + 1023) / 1024;   // 49 blocks — all co-resident

    dim3 gg((N + 63) / 64, 4);    // 64-row tiles: 782 x-blocks
    gemm3_hist_kernel<<<gg, 256>>>(E, qW, kW, vW, rows, N, Eg);   // 1
    scan_fused<<<nb, 1024>>>(N);                                  // 2
    scatter_kernel<<<(Eg + 255) / 256, 256>>>(rows, cols, Eg);    // 3
    attn_kernel<<<(N + 7) / 8, 256>>>((float*)d_out, N);          // 4 <- ncu slot
}

// round 17
// speedup vs baseline: 1.0694x; 1.0694x over previous
#include <cuda_runtime.h>
#include <cuda_bf16.h>

#define N_NODES 50000
#define N_EDGES 800000
#define LATDIM  128

typedef unsigned long long ull;

// ---- scratch (static device globals: the sanctioned no-alloc workaround) ----
__device__ float g_Q[N_NODES * LATDIM];
__device__ float g_K[N_NODES * LATDIM];
__device__ float g_V[N_NODES * LATDIM];
__device__ int   g_cnt[N_NODES];       // zero-init; re-zeroed by scan each run
__device__ int   g_bsum[64];           // lookback slots: 0 = unpublished, else total+1
__device__ int   g_rowptr[N_NODES + 1];
__device__ int   g_fill[N_NODES];
__device__ int   g_adj[N_EDGES];

// ---- packed f32x2 helpers (base sm_103 PTX — no 'a' features) ----
__device__ __forceinline__ ull pack2(float lo, float hi) {
    ull r;
    asm("mov.b64 %0, {%1, %2};" : "=l"(r)
        : "r"(__float_as_uint(lo)), "r"(__float_as_uint(hi)));
    return r;
}
__device__ __forceinline__ void fma2(ull& d, ull a, ull b) {
    asm("fma.rn.f32x2 %0, %1, %2, %3;" : "=l"(d) : "l"(a), "l"(b), "l"(d));
}
__device__ __forceinline__ void unpack2(ull v, float& lo, float& hi) {
    unsigned ulo, uhi;
    asm("mov.b64 {%0, %1}, %2;" : "=r"(ulo), "=r"(uhi) : "l"(v));
    lo = __uint_as_float(ulo);
    hi = __uint_as_float(uhi);
}

// ============================================================
// Histogram (own kernel again — runs on the side stream, overlapped
// with the GEMM; it only needs `rows`).
// ============================================================
__global__ void hist_kernel(const int* __restrict__ rows, int nE) {
    int e = blockIdx.x * blockDim.x + threadIdx.x;
    if (e < nE) atomicAdd(&g_cnt[rows[e]], 1);
}

// ============================================================
// Kernel: Q/K/V projection (locked-in R10 GEMM: scalar FFMA2,
// conflict-free B LDS, A register prefetch — 104us, 62% of the fp32
// issue floor; k-pair x2, pre-dup, and occ-3 variants all regressed).
// grid = (ceil(N/128), 3).
// ============================================================
__global__ __launch_bounds__(256, 2)
void gemm3_kernel(const float* __restrict__ E,
                  const float* __restrict__ qW,
                  const float* __restrict__ kW,
                  const float* __restrict__ vW,
                  int N)
{
    __shared__ float As[32][132];   // A tile transposed: As[k][row]
    __shared__ float Bs[32][128];   // W tile: Bs[k][col]

    const float* W   = (blockIdx.y == 0) ? qW : (blockIdx.y == 1 ? kW : vW);
    float*       Out = (blockIdx.y == 0) ? g_Q : (blockIdx.y == 1 ? g_K : g_V);

    const int row0 = blockIdx.x * 128;
    const int tid  = threadIdx.x;
    const int tr   = (tid >> 4) << 3;   // thread row base (0..120)
    const int tc   = (tid & 15) << 2;   // col blocks [tc,tc+4) and [tc+64,tc+68)
    const int kq   = (tid & 7) * 4;     // A-load k offset
    const int rb   = tid >> 3;          // A-load row base

    ull acc[8][4];
#pragma unroll
    for (int i = 0; i < 8; i++)
#pragma unroll
        for (int j = 0; j < 4; j++) acc[i][j] = 0ULL;

    // prefetch A chunk 0 into registers
    float4 aq[4];
#pragma unroll
    for (int rr = 0; rr < 4; rr++) {
        int grow = row0 + rb + rr * 32;
        aq[rr] = (grow < N)
            ? __ldg((const float4*)(E + (size_t)grow * LATDIM + kq))
            : make_float4(0.f, 0.f, 0.f, 0.f);
    }

    for (int c = 0; c < 4; c++) {
        const int kc = c * 32;
        __syncthreads();                // previous chunk's compute fully done

        // B chunk load + store (W is L2-resident after wave 1)
#pragma unroll
        for (int v = tid; v < 32 * 32; v += 256) {
            int k = v >> 5, c4 = v & 31;
            *(float4*)&Bs[k][c4 * 4] =
                __ldg((const float4*)(W + (size_t)(kc + k) * LATDIM) + c4);
        }
        // A chunk store from prefetched registers (transposed)
#pragma unroll
        for (int rr = 0; rr < 4; rr++) {
            int r = rb + rr * 32;
            As[kq + 0][r] = aq[rr].x;
            As[kq + 1][r] = aq[rr].y;
            As[kq + 2][r] = aq[rr].z;
            As[kq + 3][r] = aq[rr].w;
        }
        __syncthreads();

        // issue next chunk's A LDGs now — latency hides under compute below
        if (c < 3) {
#pragma unroll
            for (int rr = 0; rr < 4; rr++) {
                int grow = row0 + rb + rr * 32;
                aq[rr] = (grow < N)
                    ? __ldg((const float4*)(E + (size_t)grow * LATDIM + kc + 32 + kq))
                    : make_float4(0.f, 0.f, 0.f, 0.f);
            }
        }

#pragma unroll 8
        for (int k = 0; k < 32; k++) {
            float4 a0 = *(const float4*)&As[k][tr];        // broadcast
            float4 a1 = *(const float4*)&As[k][tr + 4];    // broadcast
            ulonglong2 bq0 = *(const ulonglong2*)&Bs[k][tc];       // contiguous
            ulonglong2 bq1 = *(const ulonglong2*)&Bs[k][tc + 64];  // contiguous
            ull bb[4] = {bq0.x, bq0.y, bq1.x, bq1.y};
            ull aa[8];
            aa[0] = pack2(a0.x, a0.x); aa[1] = pack2(a0.y, a0.y);
            aa[2] = pack2(a0.z, a0.z); aa[3] = pack2(a0.w, a0.w);
            aa[4] = pack2(a1.x, a1.x); aa[5] = pack2(a1.y, a1.y);
            aa[6] = pack2(a1.z, a1.z); aa[7] = pack2(a1.w, a1.w);
#pragma unroll
            for (int i = 0; i < 8; i++) {
                fma2(acc[i][0], aa[i], bb[0]);
                fma2(acc[i][1], aa[i], bb[1]);
                fma2(acc[i][2], aa[i], bb[2]);
                fma2(acc[i][3], aa[i], bb[3]);
            }
        }
    }

#pragma unroll
    for (int i = 0; i < 8; i++) {
        int grow = row0 + tr + i;
        if (grow < N) {
            float o[8];
#pragma unroll
            for (int j = 0; j < 4; j++) unpack2(acc[i][j], o[2 * j], o[2 * j + 1]);
            *(float4*)(Out + (size_t)grow * LATDIM + tc)      = make_float4(o[0], o[1], o[2], o[3]);
            *(float4*)(Out + (size_t)grow * LATDIM + tc + 64) = make_float4(o[4], o[5], o[6], o[7]);
        }
    }
}

// ============================================================
// Single-launch exclusive scan with inter-block lookback (49 blocks,
// all co-resident: 49 < 148 SMs, spin-wait deadlock-free).
// ============================================================
__global__ __launch_bounds__(1024)
void scan_fused(int n) {
    __shared__ int warp_sums[32];
    __shared__ int s_offset;
    const int tid  = threadIdx.x;
    const int lane = tid & 31;
    const int wid  = tid >> 5;
    const int bid  = blockIdx.x;
    const int i    = bid * 1024 + tid;

    int v = (i < n) ? g_cnt[i] : 0;

    int s = v;
#pragma unroll
    for (int o = 1; o < 32; o <<= 1) {
        int t = __shfl_up_sync(0xffffffffu, s, o);
        if (lane >= o) s += t;
    }
    if (lane == 31) warp_sums[wid] = s;
    __syncthreads();
    if (wid == 0) {
        int w = warp_sums[lane];
#pragma unroll
        for (int o = 1; o < 32; o <<= 1) {
            int t = __shfl_up_sync(0xffffffffu, w, o);
            if (lane >= o) w += t;
        }
        warp_sums[lane] = w;
    }
    __syncthreads();
    int incl = s + (wid > 0 ? warp_sums[wid - 1] : 0);

    if (tid == 1023) atomicExch(&g_bsum[bid], incl + 1);
    if (tid == 0) s_offset = 0;
    __syncthreads();

    if (tid < bid) {
        int pv;
        do { pv = atomicAdd(&g_bsum[tid], 0); } while (pv == 0);
        atomicAdd(&s_offset, pv - 1);
    }
    __syncthreads();

    int r = s_offset + incl - v;
    if (i < n) {
        g_rowptr[i] = r;
        g_fill[i]   = r;
        g_cnt[i]    = 0;           // re-zero for next call's histogram
    } else if (i == n) {
        g_rowptr[n] = r;
    }
}

__global__ void scatter_kernel(const int* __restrict__ rows,
                               const int* __restrict__ cols, int nE) {
    int e = blockIdx.x * blockDim.x + threadIdx.x;
    if (e < 64) g_bsum[e] = 0;     // reset lookback slots for next call
    if (e < nE) {
        int r = rows[e];
        int pos = atomicAdd(&g_fill[r], 1);
        g_adj[pos] = cols[e];
    }
}

// ============================================================
// Kernel 2: fused per-node attention. One warp per node, 2-edge
// unroll (measured optimum of the MLP/occupancy tradeoff).
// ============================================================
__global__ void attn_kernel(float* __restrict__ out, int N) {
    int warp = (blockIdx.x * blockDim.x + threadIdx.x) >> 5;
    int lane = threadIdx.x & 31;
    if (warp >= N) return;

    const float4 q = __ldg((const float4*)(g_Q + (size_t)warp * LATDIM) + lane);
    int beg = g_rowptr[warp];
    int end = g_rowptr[warp + 1];

    float ax = 0.f, ay = 0.f, az = 0.f, aw = 0.f, denom = 0.f;

    int i = beg;
    for (; i + 2 <= end; i += 2) {
        int c0 = __ldg(g_adj + i);
        int c1 = __ldg(g_adj + i + 1);
        const float4 k0 = __ldg((const float4*)(g_K + (size_t)c0 * LATDIM) + lane);
        const float4 v0 = __ldg((const float4*)(g_V + (size_t)c0 * LATDIM) + lane);
        const float4 k1 = __ldg((const float4*)(g_K + (size_t)c1 * LATDIM) + lane);
        const float4 v1 = __ldg((const float4*)(g_V + (size_t)c1 * LATDIM) + lane);

        float p0 = q.x * k0.x + q.y * k0.y + q.z * k0.z + q.w * k0.w;
        float p1 = q.x * k1.x + q.y * k1.y + q.z * k1.z + q.w * k1.w;
        p0 += __shfl_xor_sync(0xffffffffu, p0, 1);
        p1 += __shfl_xor_sync(0xffffffffu, p1, 1);
        p0 += __shfl_xor_sync(0xffffffffu, p0, 2);
        p1 += __shfl_xor_sync(0xffffffffu, p1, 2);
        p0 += __shfl_xor_sync(0xffffffffu, p0, 4);
        p1 += __shfl_xor_sync(0xffffffffu, p1, 4);
        p0 = fminf(fmaxf(p0, -10.f), 10.f);
        p1 = fminf(fmaxf(p1, -10.f), 10.f);
        float e0 = __expf(p0);
        float e1 = __expf(p1);
        denom += e0 + e1;
        ax = fmaf(e0, v0.x, ax); ax = fmaf(e1, v1.x, ax);
        ay = fmaf(e0, v0.y, ay); ay = fmaf(e1, v1.y, ay);
        az = fmaf(e0, v0.z, az); az = fmaf(e1, v1.z, az);
        aw = fmaf(e0, v0.w, aw); aw = fmaf(e1, v1.w, aw);
    }
    if (i < end) {
        int c = __ldg(g_adj + i);
        const float4 k4 = __ldg((const float4*)(g_K + (size_t)c * LATDIM) + lane);
        const float4 v4 = __ldg((const float4*)(g_V + (size_t)c * LATDIM) + lane);
        float p = q.x * k4.x + q.y * k4.y + q.z * k4.z + q.w * k4.w;
        p += __shfl_xor_sync(0xffffffffu, p, 1);
        p += __shfl_xor_sync(0xffffffffu, p, 2);
        p += __shfl_xor_sync(0xffffffffu, p, 4);
        p = fminf(fmaxf(p, -10.f), 10.f);
        float e = __expf(p);
        denom += e;
        ax = fmaf(e, v4.x, ax);
        ay = fmaf(e, v4.y, ay);
        az = fmaf(e, v4.z, az);
        aw = fmaf(e, v4.w, aw);
    }

    float inv = 1.f / (denom + 1e-8f);
    float4 o = make_float4(ax * inv, ay * inv, az * inv, aw * inv);
    *((float4*)out + (size_t)warp * 32 + lane) = o;
}

// ============================================================
// Launch: fork/join two streams inside capture. The CSR chain
// (hist -> scan -> scatter, ~21us, L2/atomic bound) runs on a side
// stream concurrently with the GEMM (104us, fma-issue bound) — they
// contend for different resources. attn joins both.
// Stream/events are host-side objects created once (no device memory).
// ============================================================
extern "C" void kernel_launch(void* const* d_in, const int* in_sizes, int n_in,
                              void* d_out, int out_size) {
    const float* E    = (const float*)d_in[0];
    const float* qW   = (const float*)d_in[1];
    const float* kW   = (const float*)d_in[2];
    const float* vW   = (const float*)d_in[3];
    const int*   rows = (const int*)d_in[4];
    const int*   cols = (const int*)d_in[5];

    int N  = in_sizes[0] / LATDIM;
    int Eg = in_sizes[4];

    int nb = (N + 1023) / 1024;   // 49 blocks — all co-resident

    static cudaStream_t s2 = nullptr;
    static cudaEvent_t  evFork = nullptr, evJoin = nullptr;
    if (s2 == nullptr) {
        cudaStreamCreateWithFlags(&s2, cudaStreamNonBlocking);
        cudaEventCreateWithFlags(&evFork, cudaEventDisableTiming);
        cudaEventCreateWithFlags(&evJoin, cudaEventDisableTiming);
    }

    // fork: side stream branches off the (capture) default stream
    cudaEventRecord(evFork, 0);
    cudaStreamWaitEvent(s2, evFork, 0);

    // side stream: CSR chain (independent of the GEMM)
    hist_kernel<<<(Eg + 255) / 256, 256, 0, s2>>>(rows, Eg);          // 1
    scan_fused<<<nb, 1024, 0, s2>>>(N);                               // 2
    scatter_kernel<<<(Eg + 255) / 256, 256, 0, s2>>>(rows, cols, Eg); // 3
    cudaEventRecord(evJoin, s2);

    // main stream: the GEMM (runs concurrently with the CSR chain)
    dim3 gg((N + 127) / 128, 3);
    gemm3_kernel<<<gg, 256>>>(E, qW, kW, vW, N);                      // 4 <- ncu slot

    // join: attn needs both the CSR and the GEMM outputs
    cudaStreamWaitEvent(0, evJoin, 0);
    attn_kernel<<<(N + 7) / 8, 256>>>((float*)d_out, N);              // 5
}